// round 16
// baseline (speedup 1.0000x reference)
#include <cuda_runtime.h>
#include <cuda_fp16.h>
#include <cstdint>

#define D_FEAT      48
#define XH_STRIDE   64            // halfs per row: 48 data + 16 zero pad = 128B
#define N_NODES_DS  100000
#define N_NODES_MAX 100001
#define N_EDGES_MAX 1600000

// CSR row pointers built each launch from the sorted COO rows array.
__device__ int d_row_ptr[N_NODES_MAX + 1];

// fp16 copy of x, rows padded to 128B. Pad region (halfs 48..63 of each row)
// is NEVER written: __device__ globals are zero-initialized at module load,
// so it stays zero -- deterministic across replays.
__device__ __align__(128) __half d_xh[(size_t)N_NODES_DS * XH_STRIDE];

// Packed per-edge metadata: {col, __float_as_int(val)} -> ONE LDG.64 per
// edge in the SpMM instead of two separate broadcast LDGs.
__device__ __align__(16) int2 d_meta[N_EDGES_MAX];

// ---------------------------------------------------------------------------
// Fused setup kernel, three concurrent sections by block range:
//   [0, conv_blocks)                      : convert x fp32 -> fp16
//   [conv_blocks, conv+pack_blocks)       : pack {col,val} -> d_meta
//   [conv+pack_blocks, ...+ptr_blocks)    : row_ptr binary search
// ---------------------------------------------------------------------------
__global__ void __launch_bounds__(256) setup_kernel(
    const float* __restrict__ x,
    const int*   __restrict__ rows,
    const int*   __restrict__ cols,
    const float* __restrict__ vals,
    int n_edges, int n_nodes, int conv_blocks, int pack_blocks)
{
    const int b = (int)blockIdx.x;
    if (b < conv_blocks) {
        // ---- convert: thread per 16B output chunk; 6 chunks per row ----
        const int tid   = b * 256 + threadIdx.x;
        const int row   = tid / 6;
        const int chunk = tid - row * 6;
        if (row >= n_nodes) return;

        const float4 f0 = *reinterpret_cast<const float4*>(
            x + (size_t)row * D_FEAT + chunk * 8);
        const float4 f1 = *reinterpret_cast<const float4*>(
            x + (size_t)row * D_FEAT + chunk * 8 + 4);
        __half2 h0 = __floats2half2_rn(f0.x, f0.y);
        __half2 h1 = __floats2half2_rn(f0.z, f0.w);
        __half2 h2 = __floats2half2_rn(f1.x, f1.y);
        __half2 h3 = __floats2half2_rn(f1.z, f1.w);
        uint4 outv;
        outv.x = *reinterpret_cast<const unsigned*>(&h0);
        outv.y = *reinterpret_cast<const unsigned*>(&h1);
        outv.z = *reinterpret_cast<const unsigned*>(&h2);
        outv.w = *reinterpret_cast<const unsigned*>(&h3);
        *reinterpret_cast<uint4*>(d_xh + (size_t)row * XH_STRIDE + chunk * 8) = outv;
    } else if (b < conv_blocks + pack_blocks) {
        // ---- pack metadata: thread per 2 edges, one int4 store ----
        const int t  = (b - conv_blocks) * 256 + threadIdx.x;
        const int i0 = t * 2;
        if (i0 + 2 <= n_edges && i0 + 2 <= N_EDGES_MAX) {
            const int2   c2 = __ldg(reinterpret_cast<const int2*>(cols + i0));
            const float2 v2 = __ldg(reinterpret_cast<const float2*>(vals + i0));
            int4 m;
            m.x = c2.x; m.y = __float_as_int(v2.x);
            m.z = c2.y; m.w = __float_as_int(v2.y);
            *reinterpret_cast<int4*>(&d_meta[i0]) = m;
        } else {
            for (int i = i0; i < n_edges && i < N_EDGES_MAX; ++i)
                d_meta[i] = make_int2(cols[i], __float_as_int(vals[i]));
        }
    } else {
        // ---- row_ptr via binary search over sorted rows ----
        const int r = (b - conv_blocks - pack_blocks) * 256 + threadIdx.x;
        if (r > n_nodes) return;
        int lo = 0, hi = n_edges;
        while (lo < hi) {
            int mid = (lo + hi) >> 1;
            if (__ldg(rows + mid) < r) lo = mid + 1;
            else                       hi = mid;
        }
        d_row_ptr[r] = lo;
    }
}

// ---------------------------------------------------------------------------
// SpMM: quarter-warp (8 lanes) per row, 4 rows/warp, fp16 1-line gathers.
//   Metadata: ONE LDG.64 of packed {col,val} per edge (broadcast within
//   group) -- one fewer instruction AND one fewer L1 wavefront per edge
//   than separate col/val loads.
//   Hot path: 8-edge chunks accumulated with HFMA2 into four half2
//   registers, flushed to fp32 accumulators once per chunk. Remainder
//   (<8 edges) uses the exact fp32 path.
// ---------------------------------------------------------------------------
__global__ void __launch_bounds__(256) spmm_csr_qw_h_kernel(
    float* __restrict__ out,
    int n_nodes)
{
    const int warp_id = (blockIdx.x * blockDim.x + threadIdx.x) >> 5;
    const int lane    = threadIdx.x & 31;
    const int g       = lane >> 3;          // group 0..3 -> row within warp
    const int sub     = lane & 7;           // lane within group
    const bool active = sub < 6;            // 6 lanes x 8 halfs = 48 features

    const int row = warp_id * 4 + g;
    if (row >= n_nodes) return;

    const int s = d_row_ptr[row];
    const int e = d_row_ptr[row + 1];

    float a0 = 0.f, a1 = 0.f, a2 = 0.f, a3 = 0.f;
    float a4 = 0.f, a5 = 0.f, a6 = 0.f, a7 = 0.f;

    const size_t hoff = (size_t)sub * 8;    // 8 halfs = 16B per lane

    int i = s;

    // ---- full 8-edge chunks: HFMA2 into half2, flush to fp32 per chunk ----
    for (; i + 8 <= e; i += 8) {
        __half2 c0 = __float2half2_rn(0.f);
        __half2 c1 = c0, c2 = c0, c3 = c0;

        #pragma unroll
        for (int j = 0; j < 8; ++j) {
            const int2 m = __ldg(&d_meta[i + j]);      // one LDG.64, broadcast
            const int   c = m.x;
            const float v = __int_as_float(m.y);
            if (active) {
                const uint4 h4 = *reinterpret_cast<const uint4*>(
                    d_xh + (size_t)c * XH_STRIDE + hoff);   // LDG.128, 1 line
                const __half2 vh = __float2half2_rn(v);
                c0 = __hfma2(*reinterpret_cast<const __half2*>(&h4.x), vh, c0);
                c1 = __hfma2(*reinterpret_cast<const __half2*>(&h4.y), vh, c1);
                c2 = __hfma2(*reinterpret_cast<const __half2*>(&h4.z), vh, c2);
                c3 = __hfma2(*reinterpret_cast<const __half2*>(&h4.w), vh, c3);
            }
        }

        if (active) {
            const float2 f0 = __half22float2(c0);
            const float2 f1 = __half22float2(c1);
            const float2 f2 = __half22float2(c2);
            const float2 f3 = __half22float2(c3);
            a0 += f0.x; a1 += f0.y;
            a2 += f1.x; a3 += f1.y;
            a4 += f2.x; a5 += f2.y;
            a6 += f3.x; a7 += f3.y;
        }
    }

    // ---- remainder (<8 edges): exact fp32 path ----
    for (; i < e; ++i) {
        const int2 m = __ldg(&d_meta[i]);
        const int   c = m.x;
        const float v = __int_as_float(m.y);
        if (active) {
            const uint4 h4 = *reinterpret_cast<const uint4*>(
                d_xh + (size_t)c * XH_STRIDE + hoff);
            const float2 f0 = __half22float2(*reinterpret_cast<const __half2*>(&h4.x));
            const float2 f1 = __half22float2(*reinterpret_cast<const __half2*>(&h4.y));
            const float2 f2 = __half22float2(*reinterpret_cast<const __half2*>(&h4.z));
            const float2 f3 = __half22float2(*reinterpret_cast<const __half2*>(&h4.w));
            a0 += v * f0.x; a1 += v * f0.y;
            a2 += v * f1.x; a3 += v * f1.y;
            a4 += v * f2.x; a5 += v * f2.y;
            a6 += v * f3.x; a7 += v * f3.y;
        }
    }

    if (active) {
        float* o = out + (size_t)row * D_FEAT + sub * 8;
        *reinterpret_cast<float4*>(o)     = make_float4(a0, a1, a2, a3);
        *reinterpret_cast<float4*>(o + 4) = make_float4(a4, a5, a6, a7);
    }
}

// ---------------------------------------------------------------------------
// kernel_launch: inputs per metadata order: t, x, rows, cols, vals.
// ---------------------------------------------------------------------------
extern "C" void kernel_launch(void* const* d_in, const int* in_sizes, int n_in,
                              void* d_out, int out_size)
{
    const float* x    = (const float*)d_in[1];
    const int*   rows = (const int*)  d_in[2];
    const int*   cols = (const int*)  d_in[3];
    const float* vals = (const float*)d_in[4];
    float*       out  = (float*)d_out;

    const int n_edges = in_sizes[4];
    const int n_nodes = out_size / D_FEAT;

    // Fused setup: convert x, pack metadata, build row_ptr -- all concurrent.
    {
        const int conv_blocks = (n_nodes * 6 + 255) / 256;
        const int pack_blocks = ((n_edges + 1) / 2 + 255) / 256;
        const int ptr_blocks  = (n_nodes + 1 + 255) / 256;
        setup_kernel<<<conv_blocks + pack_blocks + ptr_blocks, 256>>>(
            x, rows, cols, vals, n_edges, n_nodes, conv_blocks, pack_blocks);
    }

    // SpMM: quarter-warp-per-row, packed metadata, HFMA2 chunks.
    {
        const int threads = 256;                           // 8 warps/block
        const int warps   = (n_nodes + 3) / 4;
        const int blocks  = (warps * 32 + threads - 1) / threads;
        spmm_csr_qw_h_kernel<<<blocks, threads>>>(out, n_nodes);
    }
}

// round 17
// speedup vs baseline: 1.1079x; 1.1079x over previous
#include <cuda_runtime.h>
#include <cuda_fp16.h>
#include <cstdint>

#define D_FEAT      48
#define XH_STRIDE   64            // halfs per row: 48 data + 16 zero pad = 128B
#define N_NODES_DS  100000
#define N_NODES_MAX 100001

// CSR row pointers built each launch from the sorted COO rows array.
__device__ int d_row_ptr[N_NODES_MAX + 1];

// fp16 copy of x, rows padded to 128B. Pad region (halfs 48..63 of each row)
// is NEVER written: __device__ globals are zero-initialized at module load,
// so it stays zero -- deterministic across replays.
__device__ __align__(128) __half d_xh[(size_t)N_NODES_DS * XH_STRIDE];

// ---------------------------------------------------------------------------
// Fused setup kernel, two concurrent sections by block range:
//   [0, conv_blocks)          : convert x fp32 -> fp16, thread per HALF ROW
//                               (6 independent LDG.128 + 3 STG.128 -> 3x the
//                               per-thread MLP of the old chunk version)
//   [conv_blocks, +ptr_blocks): row_ptr binary search over sorted rows
// ---------------------------------------------------------------------------
__global__ void __launch_bounds__(256) setup_kernel(
    const float* __restrict__ x,
    const int*   __restrict__ rows,
    int n_edges, int n_nodes, int conv_blocks)
{
    const int b = (int)blockIdx.x;
    if (b < conv_blocks) {
        // ---- convert: thread per half row (24 floats -> 24 halfs) ----
        const int tid  = b * 256 + threadIdx.x;
        const int row  = tid >> 1;
        const int half = tid & 1;           // 0: features 0..23, 1: 24..47
        if (row >= n_nodes) return;

        const float* xp = x + (size_t)row * D_FEAT + half * 24;
        const float4 f0 = *reinterpret_cast<const float4*>(xp);
        const float4 f1 = *reinterpret_cast<const float4*>(xp + 4);
        const float4 f2 = *reinterpret_cast<const float4*>(xp + 8);
        const float4 f3 = *reinterpret_cast<const float4*>(xp + 12);
        const float4 f4 = *reinterpret_cast<const float4*>(xp + 16);
        const float4 f5 = *reinterpret_cast<const float4*>(xp + 20);

        __half2 h[12];
        h[0]  = __floats2half2_rn(f0.x, f0.y);
        h[1]  = __floats2half2_rn(f0.z, f0.w);
        h[2]  = __floats2half2_rn(f1.x, f1.y);
        h[3]  = __floats2half2_rn(f1.z, f1.w);
        h[4]  = __floats2half2_rn(f2.x, f2.y);
        h[5]  = __floats2half2_rn(f2.z, f2.w);
        h[6]  = __floats2half2_rn(f3.x, f3.y);
        h[7]  = __floats2half2_rn(f3.z, f3.w);
        h[8]  = __floats2half2_rn(f4.x, f4.y);
        h[9]  = __floats2half2_rn(f4.z, f4.w);
        h[10] = __floats2half2_rn(f5.x, f5.y);
        h[11] = __floats2half2_rn(f5.z, f5.w);

        uint4* dst = reinterpret_cast<uint4*>(
            d_xh + (size_t)row * XH_STRIDE + half * 24);
        const unsigned* hu = reinterpret_cast<const unsigned*>(h);
        dst[0] = make_uint4(hu[0], hu[1], hu[2],  hu[3]);
        dst[1] = make_uint4(hu[4], hu[5], hu[6],  hu[7]);
        dst[2] = make_uint4(hu[8], hu[9], hu[10], hu[11]);
    } else {
        // ---- row_ptr via binary search over sorted rows ----
        const int r = (b - conv_blocks) * 256 + threadIdx.x;
        if (r > n_nodes) return;
        int lo = 0, hi = n_edges;
        while (lo < hi) {
            int mid = (lo + hi) >> 1;
            if (__ldg(rows + mid) < r) lo = mid + 1;
            else                       hi = mid;
        }
        d_row_ptr[r] = lo;
    }
}

// ---------------------------------------------------------------------------
// SpMM: SIX-lane group per row, 5 rows/warp (lanes 30,31 idle).
//   48 halfs = 96B = exactly 6 lanes x 16B: every gather lane is live (no
//   'active' predicate) and the LDG.128 touches one 128B line (offsets
//   0..80B within the aligned row). 5 rows/warp cuts total warp-iterations
//   ~18% vs the 4-row/8-lane layout (padding = max over 5 degrees).
//   Hot path: 8-edge chunks accumulated with HFMA2 into four half2
//   registers, flushed to fp32 accumulators once per chunk (numerics
//   identical to R15). Remainder (<8 edges) uses the exact fp32 path.
// ---------------------------------------------------------------------------
__global__ void __launch_bounds__(256) spmm_csr_g6_kernel(
    const int*   __restrict__ cols,
    const float* __restrict__ vals,
    float*       __restrict__ out,
    int n_nodes)
{
    const int warp_id = (blockIdx.x * blockDim.x + threadIdx.x) >> 5;
    const int lane    = threadIdx.x & 31;
    const int g       = lane / 6;           // group 0..4 -> row within warp
    const int sub     = lane - g * 6;       // lane within group, 0..5
    if (g >= 5) return;                     // lanes 30,31 idle

    const int row = warp_id * 5 + g;
    if (row >= n_nodes) return;

    const int s = d_row_ptr[row];
    const int e = d_row_ptr[row + 1];

    float a0 = 0.f, a1 = 0.f, a2 = 0.f, a3 = 0.f;
    float a4 = 0.f, a5 = 0.f, a6 = 0.f, a7 = 0.f;

    const size_t hoff = (size_t)sub * 8;    // 8 halfs = 16B per lane

    int i = s;

    // ---- full 8-edge chunks: HFMA2 into half2, flush to fp32 per chunk ----
    for (; i + 8 <= e; i += 8) {
        __half2 c0 = __float2half2_rn(0.f);
        __half2 c1 = c0, c2 = c0, c3 = c0;

        #pragma unroll
        for (int j = 0; j < 8; ++j) {
            const int   c = __ldg(cols + i + j);   // uniform within group
            const float v = __ldg(vals + i + j);
            const uint4 h4 = *reinterpret_cast<const uint4*>(
                d_xh + (size_t)c * XH_STRIDE + hoff);   // LDG.128, 1 line
            const __half2 vh = __float2half2_rn(v);
            c0 = __hfma2(*reinterpret_cast<const __half2*>(&h4.x), vh, c0);
            c1 = __hfma2(*reinterpret_cast<const __half2*>(&h4.y), vh, c1);
            c2 = __hfma2(*reinterpret_cast<const __half2*>(&h4.z), vh, c2);
            c3 = __hfma2(*reinterpret_cast<const __half2*>(&h4.w), vh, c3);
        }

        const float2 f0 = __half22float2(c0);
        const float2 f1 = __half22float2(c1);
        const float2 f2 = __half22float2(c2);
        const float2 f3 = __half22float2(c3);
        a0 += f0.x; a1 += f0.y;
        a2 += f1.x; a3 += f1.y;
        a4 += f2.x; a5 += f2.y;
        a6 += f3.x; a7 += f3.y;
    }

    // ---- remainder (<8 edges): exact fp32 path ----
    for (; i < e; ++i) {
        const int   c = __ldg(cols + i);
        const float v = __ldg(vals + i);
        const uint4 h4 = *reinterpret_cast<const uint4*>(
            d_xh + (size_t)c * XH_STRIDE + hoff);
        const float2 f0 = __half22float2(*reinterpret_cast<const __half2*>(&h4.x));
        const float2 f1 = __half22float2(*reinterpret_cast<const __half2*>(&h4.y));
        const float2 f2 = __half22float2(*reinterpret_cast<const __half2*>(&h4.z));
        const float2 f3 = __half22float2(*reinterpret_cast<const __half2*>(&h4.w));
        a0 += v * f0.x; a1 += v * f0.y;
        a2 += v * f1.x; a3 += v * f1.y;
        a4 += v * f2.x; a5 += v * f2.y;
        a6 += v * f3.x; a7 += v * f3.y;
    }

    float* o = out + (size_t)row * D_FEAT + sub * 8;
    *reinterpret_cast<float4*>(o)     = make_float4(a0, a1, a2, a3);
    *reinterpret_cast<float4*>(o + 4) = make_float4(a4, a5, a6, a7);
}

// ---------------------------------------------------------------------------
// kernel_launch: inputs per metadata order: t, x, rows, cols, vals.
// ---------------------------------------------------------------------------
extern "C" void kernel_launch(void* const* d_in, const int* in_sizes, int n_in,
                              void* d_out, int out_size)
{
    const float* x    = (const float*)d_in[1];
    const int*   rows = (const int*)  d_in[2];
    const int*   cols = (const int*)  d_in[3];
    const float* vals = (const float*)d_in[4];
    float*       out  = (float*)d_out;

    const int n_edges = in_sizes[4];
    const int n_nodes = out_size / D_FEAT;

    // Fused setup: convert x to fp16 AND build row_ptr, concurrently.
    {
        const int conv_blocks = (n_nodes * 2 + 255) / 256;
        const int ptr_blocks  = (n_nodes + 1 + 255) / 256;
        setup_kernel<<<conv_blocks + ptr_blocks, 256>>>(
            x, rows, n_edges, n_nodes, conv_blocks);
    }

    // SpMM: 6-lane group per row, 5 rows/warp.
    {
        const int threads = 256;                           // 8 warps/block
        const int warps   = (n_nodes + 4) / 5;
        const int blocks  = (warps * 32 + threads - 1) / threads;
        spmm_csr_g6_kernel<<<blocks, threads>>>(cols, vals, out, n_nodes);
    }
}